// round 10
// baseline (speedup 1.0000x reference)
#include <cuda_runtime.h>
#include <cuda_bf16.h>
#include <math.h>
#include <stdint.h>

// R10: hoist all bf16 split3 out of the conv hot loop.
//  - weights pre-split+packed into k-pair u32 planes by prep_w_split
//  - activations pre-split into 3 u16 planes by act_split (relu pre-applied
//    where the consuming conv needs it)
// Hot loop arithmetic is now: fragment LDS + MMA + per-tile drain only.
// Values are bit-identical to R9 (same split3), so rel_err should hold ~5.5e-5.

// ---------------- scratch (device globals: allowed; no allocs) ----------------
__device__ float g_c1 [4*256*128*128];   // conv1 out fp32            64 MB
__device__ float g_c2 [4*128* 64* 64];   // conv2 out fp32             8 MB
__device__ float g_c3 [4*128* 32* 32];   // conv3 out fp32             2 MB
__device__ float g_lat[4*256*128*128];   // lat out fp32 (relu'd)     64 MB
__device__ float g_ow [4* 73*128*128];   // pred out fp32             19 MB
__device__ float g_wt [4*144*64];        // dcn_w transposed

__device__ unsigned g_wTs[3317760];      // conv weights: 3 packed planes / conv

// split activation planes (3 consecutive planes each)
__device__ unsigned short g_curS [3* 4194304];   //  25 MB
__device__ unsigned short g_supS [3* 4194304];   //  25 MB
__device__ unsigned short g_c1Sr [3*16777216];   // 100 MB (raw, for conv2)
__device__ unsigned short g_c1Sa [3*16777216];   // 100 MB (relu, for lat)
__device__ unsigned short g_c2Sr [3* 2097152];   //  12.6 MB (raw, for conv3)
__device__ unsigned short g_c2Sa [3* 2097152];   //  12.6 MB (relu, for lat)
__device__ unsigned short g_c3Sa [3*  524288];   //   3.1 MB (relu, for lat)
__device__ unsigned short g_latS [3*16777216];   // 100 MB (for pred)

// packed-weight offsets (u32 words): 3*(K/2)*MP per conv
#define WS_C1   0
#define WS_C2   442368
#define WS_C3   884736
#define WS_LAT  1105920
#define WS_PRED 2875392

// 3-way bf16 split: v = s0 + s1 + s2
__device__ __forceinline__ void split3(float v, unsigned short& s0,
                                       unsigned short& s1, unsigned short& s2)
{
    __nv_bfloat16 b0 = __float2bfloat16_rn(v);
    float r = v - __bfloat162float(b0);
    __nv_bfloat16 b1 = __float2bfloat16_rn(r);
    r -= __bfloat162float(b1);
    __nv_bfloat16 b2 = __float2bfloat16_rn(r);
    s0 = __bfloat16_as_ushort(b0);
    s1 = __bfloat16_as_ushort(b1);
    s2 = __bfloat16_as_ushort(b2);
}
__device__ __forceinline__ unsigned packu(unsigned short lo, unsigned short hi)
{
    return (unsigned)lo | ((unsigned)hi << 16);   // even k in low half
}

__device__ __forceinline__ void mma_bf16(float (&d)[4], const unsigned (&a)[4],
                                         const unsigned (&b)[2])
{
    asm volatile(
        "mma.sync.aligned.m16n8k16.row.col.f32.bf16.bf16.f32 "
        "{%0,%1,%2,%3},{%4,%5,%6,%7},{%8,%9},{%0,%1,%2,%3};"
        : "+f"(d[0]), "+f"(d[1]), "+f"(d[2]), "+f"(d[3])
        : "r"(a[0]), "r"(a[1]), "r"(a[2]), "r"(a[3]), "r"(b[0]), "r"(b[1]));
}

// ---- weight prep: [COUT][K] -> 3 packed planes [K/2][MP] (u32 k-pairs) ----
__global__ void prep_w_split(const float* __restrict__ w, unsigned* __restrict__ o,
                             int K, int COUT, int MP)
{
    int idx = blockIdx.x * 256 + threadIdx.x;
    int PS  = (K / 2) * MP;
    if (idx >= PS) return;
    int m  = idx % MP;
    int kp = idx / MP;
    float v0 = 0.f, v1 = 0.f;
    if (m < COUT) {
        v0 = w[(size_t)m * K + 2 * kp];
        v1 = w[(size_t)m * K + 2 * kp + 1];
    }
    unsigned short a0, a1, a2, b0, b1, b2;
    split3(v0, a0, a1, a2);
    split3(v1, b0, b1, b2);
    o[idx]          = packu(a0, b0);
    o[PS + idx]     = packu(a1, b1);
    o[2 * PS + idx] = packu(a2, b2);
}

// ---- activation split: fp32 -> 3 u16 planes (optional relu first) ----
__global__ void act_split(const float* __restrict__ in,
                          unsigned short* __restrict__ s, int n, int relu)
{
    int i = blockIdx.x * 256 + threadIdx.x;
    if (i >= n) return;
    float v = in[i];
    if (relu) v = fmaxf(v, 0.f);
    unsigned short a0, a1, a2;
    split3(v, a0, a1, a2);
    s[i]         = a0;
    s[n + i]     = a1;
    s[2 * n + i] = a2;
}

// ---------------- bf16x6 tensor-core implicit-GEMM 3x3 conv ----------------
// Same layout/pipeline as R9; gathers read pre-split planes (zero split math).
template<int MODE, int CIN, int COUT, int MP, int STRIDE, int OH, int OW, bool HASBIAS, bool RELU>
__global__ __launch_bounds__(256, 2)
void conv3x3_bf(const unsigned short* __restrict__ q0,
                const unsigned short* __restrict__ q1,
                const unsigned short* __restrict__ q2,
                const unsigned* __restrict__ wTs,
                const float* __restrict__ bias, float* __restrict__ out)
{
    constexpr int K     = CIN * 9;
    constexpr int KT    = K / 16;
    constexpr int IH    = OH * STRIDE;
    constexpr int IW    = OW * STRIDE;
    constexpr int OHW   = OH * OW;
    constexpr int PR    = 136;
    constexpr int PLANE = 8 * PR;
    constexpr int APS   = (K / 2) * MP;                    // weight plane stride
    constexpr size_t PL0 = (MODE == 2) ? 16777216 : (size_t)4 * CIN * IH * IW / (MODE == 1 ? 2 : 1);
    constexpr size_t PL1 = (MODE == 2) ? 2097152 : ((MODE == 1) ? PL0 : 0);
    constexpr size_t PL2 = (MODE == 2) ? 524288 : 0;

    extern __shared__ unsigned sm[];

    const int tid  = threadIdx.x;
    const int lane = tid & 31;
    const int wid  = tid >> 5;
    const int l4   = lane & 3;
    const int l8   = lane >> 2;
    const int m0   = blockIdx.y * 128;
    const int n0   = blockIdx.x * 128;
    const int warp_m = (wid >> 2) * 64;
    const int warp_n = (wid & 3) * 32;

    auto Ab = [&](int buf, int p) { return sm + ((buf * 2 + 0) * 3 + p) * PLANE; };
    auto Bb = [&](int buf, int p) { return sm + ((buf * 2 + 1) * 3 + p) * PLANE; };

    const int nn  = tid & 127;
    const int kk  = tid >> 7;
    const int n   = n0 + nn;
    const int b   = n / OHW;
    const int rem = n - b * OHW;
    const int oy  = rem / OW;
    const int ox  = rem - oy * OW;
    const int iy0 = oy * STRIDE - 1;
    const int ix0 = ox * STRIDE - 1;
    int ci0 = (kk * 8) / 9;
    int rr0 = kk * 8 - ci0 * 9;

    unsigned aw[3][4];                 // packed A words
    unsigned short bu[3][8];           // B u16 halves per plane

    float acc[4][4][4];
    #pragma unroll
    for (int i = 0; i < 4; i++)
        #pragma unroll
        for (int j = 0; j < 4; j++)
            #pragma unroll
            for (int r = 0; r < 4; r++) acc[i][j][r] = 0.f;

    auto gatherA = [&](int kt) {
        const unsigned* pa = wTs + (size_t)(kt * 8 + wid) * MP + m0 + lane;
        #pragma unroll
        for (int p = 0; p < 3; p++)
            #pragma unroll
            for (int c = 0; c < 4; c++)
                aw[p][c] = pa[p * APS + 32 * c];
    };

    auto gatherB = [&]() {
        #pragma unroll
        for (int h = 0; h < 8; h++) {
            int rr = rr0 + h, ci = ci0;
            if (rr >= 9) { rr -= 9; ci += 1; }
            int ky = (rr * 11) >> 5;
            int kx = rr - ky * 3;
            int iy = iy0 + ky;
            int ix = ix0 + kx;
            bool ok = ((unsigned)iy < (unsigned)IH) && ((unsigned)ix < (unsigned)IW);
            unsigned short v0 = 0, v1 = 0, v2 = 0;
            if (ok) {
                const unsigned short* q;
                size_t PL, idx;
                if (MODE == 0) {
                    q = q0; PL = PL0;
                    idx = (((size_t)b * CIN + ci) * IH + iy) * IW + ix;
                } else if (MODE == 1) {
                    q = (ci < 64) ? q0 : q1; PL = PL0;
                    idx = (((size_t)b * 64 + (ci & 63)) * 128 + iy) * 128 + ix;
                } else {
                    if (ci < 256) {
                        q = q0; PL = PL0;
                        idx = (((size_t)b * 256 + ci) * 128 + iy) * 128 + ix;
                    } else if (ci < 384) {
                        q = q1; PL = PL1;
                        idx = (((size_t)b * 128 + (ci - 256)) * 64 + (iy >> 1)) * 64 + (ix >> 1);
                    } else {
                        q = q2; PL = PL2;
                        idx = (((size_t)b * 128 + (ci - 384)) * 32 + (iy >> 2)) * 32 + (ix >> 2);
                    }
                }
                v0 = q[idx]; v1 = q[idx + PL]; v2 = q[idx + 2 * PL];
            }
            bu[0][h] = v0; bu[1][h] = v1; bu[2][h] = v2;
        }
        ci0 += 1; rr0 += 7;
        if (rr0 >= 9) { rr0 -= 9; ci0 += 1; }
    };

    auto storeA = [&](int buf) {
        unsigned idx = wid * PR + lane;
        #pragma unroll
        for (int p = 0; p < 3; p++)
            #pragma unroll
            for (int c = 0; c < 4; c++)
                Ab(buf, p)[idx + 32 * c] = aw[p][c];
    };

    auto storeB = [&](int buf) {
        #pragma unroll
        for (int t = 0; t < 4; t++) {
            unsigned idx = (kk * 4 + t) * PR + nn;
            Bb(buf, 0)[idx] = packu(bu[0][2 * t], bu[0][2 * t + 1]);
            Bb(buf, 1)[idx] = packu(bu[1][2 * t], bu[1][2 * t + 1]);
            Bb(buf, 2)[idx] = packu(bu[2][2 * t], bu[2][2 * t + 1]);
        }
    };

    auto compute = [&](int buf) {
        unsigned bf[3][4][2];
        #pragma unroll
        for (int j = 0; j < 4; j++) {
            int nj = warp_n + 8 * j + l8;
            #pragma unroll
            for (int p = 0; p < 3; p++) {
                bf[p][j][0] = Bb(buf, p)[l4 * PR + nj];
                bf[p][j][1] = Bb(buf, p)[(l4 + 4) * PR + nj];
            }
        }
        #pragma unroll
        for (int i = 0; i < 4; i++) {
            int mi = warp_m + 16 * i + l8;
            unsigned av[3][4];
            #pragma unroll
            for (int p = 0; p < 3; p++) {
                av[p][0] = Ab(buf, p)[l4 * PR + mi];
                av[p][1] = Ab(buf, p)[l4 * PR + mi + 8];
                av[p][2] = Ab(buf, p)[(l4 + 4) * PR + mi];
                av[p][3] = Ab(buf, p)[(l4 + 4) * PR + mi + 8];
            }
            #pragma unroll
            for (int j = 0; j < 4; j++) {
                // per-tile temp: TC rounding confined; long-K accum in fp32-RN
                float tmp[4] = {0.f, 0.f, 0.f, 0.f};
                mma_bf16(tmp, av[2], bf[0][j]);
                mma_bf16(tmp, av[0], bf[2][j]);
                mma_bf16(tmp, av[1], bf[1][j]);
                mma_bf16(tmp, av[1], bf[0][j]);
                mma_bf16(tmp, av[0], bf[1][j]);
                mma_bf16(tmp, av[0], bf[0][j]);
                #pragma unroll
                for (int r = 0; r < 4; r++)
                    acc[i][j][r] += tmp[r];
            }
        }
    };

    gatherA(0); gatherB();
    storeA(0);  storeB(0);
    __syncthreads();
    #pragma unroll 1
    for (int kt = 0; kt < KT; kt++) {
        const int cur = kt & 1;
        if (kt + 1 < KT) { gatherA(kt + 1); gatherB(); }
        compute(cur);
        if (kt + 1 < KT) { storeA(cur ^ 1); storeB(cur ^ 1); }
        __syncthreads();
    }

    #pragma unroll
    for (int i = 0; i < 4; i++) {
        #pragma unroll
        for (int half = 0; half < 2; half++) {
            int m = m0 + warp_m + 16 * i + l8 + 8 * half;
            if (m >= COUT) continue;
            float bv = HASBIAS ? bias[m] : 0.f;
            #pragma unroll
            for (int j = 0; j < 4; j++) {
                int n2 = n0 + warp_n + 8 * j + 2 * l4;
                int b2 = n2 / OHW;
                int r2 = n2 - b2 * OHW;
                float v0 = acc[i][j][half * 2 + 0] + bv;
                float v1 = acc[i][j][half * 2 + 1] + bv;
                if (RELU) { v0 = fmaxf(v0, 0.f); v1 = fmaxf(v1, 0.f); }
                *(float2*)&out[((size_t)b2 * COUT + m) * OHW + r2] = make_float2(v0, v1);
            }
        }
    }
}

#define CONV_SMEM (2 * 2 * 3 * (8 * 136) * 4)

// ---------------- dcn weight transpose ----------------
__global__ void transpose_dcn_w(const float* __restrict__ dcn_w, float* __restrict__ wt)
{
    int e = blockIdx.x * 256 + threadIdx.x;
    if (e >= 4 * 144 * 64) return;
    int o   = e & 63;
    int gck = e >> 6;
    int g   = gck / 144;
    int ck  = gck - g * 144;
    int c   = ck / 9;
    int k   = ck - c * 9;
    wt[e] = dcn_w[((size_t)(o * 64 + g * 16 + c)) * 9 + k];
}

// ---------------- deformable conv (dg=4, Cg=16, K=3) ----------------
__global__ __launch_bounds__(128)
void deform_kernel(const float* __restrict__ sup,
                   const float* __restrict__ ow,
                   const float* __restrict__ wt,
                   float* __restrict__ out)
{
    __shared__ float s[144 * 32];
    const int t  = threadIdx.x;
    const int p0 = blockIdx.x * 32;
    const int og = t & 15;
    const int pg = t >> 4;

    float acc[4][4] = {};

    for (int g = 0; g < 4; g++) {
        if (g) __syncthreads();
        for (int tt = t; tt < 288; tt += 128) {
            int px = tt & 31;
            int k  = tt >> 5;
            int p  = p0 + px;
            int b  = p >> 14;
            int yx = p & 16383;
            int yy = yx >> 7;
            int xx = yx & 127;
            int ky = k / 3;
            int kx = k - ky * 3;
            int och = (g * 9 + k) * 2;
            const float* owb = ow + ((size_t)b * 73 + och) * 16384 + yx;
            float dy = owb[0];
            float dx = owb[16384];
            float py  = (float)(yy + ky - 1) + dy;
            float pxf = (float)(xx + kx - 1) + dx;
            float y0f = floorf(py), x0f = floorf(pxf);
            int   y0  = (int)y0f,  x0  = (int)x0f;
            float wy1 = py  - y0f, wx1 = pxf - x0f;
            float wy0 = 1.f - wy1, wx0 = 1.f - wx1;
            bool vy0 = (unsigned)y0       < 128u;
            bool vy1 = (unsigned)(y0 + 1) < 128u;
            bool vx0 = (unsigned)x0       < 128u;
            bool vx1 = (unsigned)(x0 + 1) < 128u;
            float w00 = (vy0 && vx0) ? wy0 * wx0 : 0.f;
            float w01 = (vy0 && vx1) ? wy0 * wx1 : 0.f;
            float w10 = (vy1 && vx0) ? wy1 * wx0 : 0.f;
            float w11 = (vy1 && vx1) ? wy1 * wx1 : 0.f;
            int yc0 = min(max(y0, 0), 127);
            int yc1 = min(max(y0 + 1, 0), 127);
            int xc0 = min(max(x0, 0), 127);
            int xc1 = min(max(x0 + 1, 0), 127);
            const float* fb = sup + ((size_t)b * 64 + g * 16) * 16384;
            int i00 = yc0 * 128 + xc0, i01 = yc0 * 128 + xc1;
            int i10 = yc1 * 128 + xc0, i11 = yc1 * 128 + xc1;
            #pragma unroll
            for (int c = 0; c < 16; c++) {
                const float* f = fb + c * 16384;
                float v = w00 * f[i00] + w01 * f[i01] + w10 * f[i10] + w11 * f[i11];
                s[(c * 9 + k) * 32 + px] = v;
            }
        }
        __syncthreads();
        const float* wg = wt + g * 144 * 64;
        #pragma unroll 4
        for (int ck = 0; ck < 144; ck++) {
            float4 v4 = *(const float4*)&s[ck * 32 + pg * 4];
            float4 w4 = __ldg((const float4*)(wg + ck * 64 + og * 4));
            float v[4]  = {v4.x, v4.y, v4.z, v4.w};
            float wv[4] = {w4.x, w4.y, w4.z, w4.w};
            #pragma unroll
            for (int i = 0; i < 4; i++)
                #pragma unroll
                for (int j = 0; j < 4; j++)
                    acc[i][j] = fmaf(v[i], wv[j], acc[i][j]);
        }
    }

    #pragma unroll
    for (int i = 0; i < 4; i++) {
        int p  = p0 + pg * 4 + i;
        int b  = p >> 14;
        int yx = p & 16383;
        #pragma unroll
        for (int j = 0; j < 4; j++) {
            int o = og * 4 + j;
            out[((size_t)b * 64 + o) * 16384 + yx] = acc[i][j];
        }
    }
}

// ---------------- weight channel: relu(ow[:,72]) ----------------
__global__ void weight_relu_kernel(const float* __restrict__ ow, float* __restrict__ out2)
{
    int i  = blockIdx.x * 256 + threadIdx.x;
    int b  = i >> 14;
    int yx = i & 16383;
    out2[i] = fmaxf(ow[((size_t)b * 73 + 72) * 16384 + yx], 0.f);
}

// ---------------- launch ----------------
extern "C" void kernel_launch(void* const* d_in, const int* in_sizes, int n_in,
                              void* d_out, int out_size)
{
    const float* cur    = (const float*)d_in[0];
    const float* sup    = (const float*)d_in[1];
    const float* off_w1 = (const float*)d_in[3];
    const float* off_w2 = (const float*)d_in[4];
    const float* off_w3 = (const float*)d_in[5];
    const float* lat_w  = (const float*)d_in[6];
    const float* lat_b  = (const float*)d_in[7];
    const float* pred_w = (const float*)d_in[8];
    const float* pred_b = (const float*)d_in[9];
    const float* dcn_w  = (const float*)d_in[10];
    float* out = (float*)d_out;

    float *c1, *c2, *c3, *lat, *owb, *wtb;
    unsigned* wTs;
    unsigned short *curS, *supS, *c1Sr, *c1Sa, *c2Sr, *c2Sa, *c3Sa, *latS;
    cudaGetSymbolAddress((void**)&c1,   g_c1);
    cudaGetSymbolAddress((void**)&c2,   g_c2);
    cudaGetSymbolAddress((void**)&c3,   g_c3);
    cudaGetSymbolAddress((void**)&lat,  g_lat);
    cudaGetSymbolAddress((void**)&owb,  g_ow);
    cudaGetSymbolAddress((void**)&wtb,  g_wt);
    cudaGetSymbolAddress((void**)&wTs,  g_wTs);
    cudaGetSymbolAddress((void**)&curS, g_curS);
    cudaGetSymbolAddress((void**)&supS, g_supS);
    cudaGetSymbolAddress((void**)&c1Sr, g_c1Sr);
    cudaGetSymbolAddress((void**)&c1Sa, g_c1Sa);
    cudaGetSymbolAddress((void**)&c2Sr, g_c2Sr);
    cudaGetSymbolAddress((void**)&c2Sa, g_c2Sa);
    cudaGetSymbolAddress((void**)&c3Sa, g_c3Sa);
    cudaGetSymbolAddress((void**)&latS, g_latS);

    cudaFuncSetAttribute(conv3x3_bf<1,128,256,256,1,128,128,false,false>,
                         cudaFuncAttributeMaxDynamicSharedMemorySize, CONV_SMEM);
    cudaFuncSetAttribute(conv3x3_bf<0,256,128,128,2,64,64,false,false>,
                         cudaFuncAttributeMaxDynamicSharedMemorySize, CONV_SMEM);
    cudaFuncSetAttribute(conv3x3_bf<0,128,128,128,2,32,32,false,false>,
                         cudaFuncAttributeMaxDynamicSharedMemorySize, CONV_SMEM);
    cudaFuncSetAttribute(conv3x3_bf<2,512,256,256,1,128,128,true,true>,
                         cudaFuncAttributeMaxDynamicSharedMemorySize, CONV_SMEM);
    cudaFuncSetAttribute(conv3x3_bf<0,256,73,128,1,128,128,true,false>,
                         cudaFuncAttributeMaxDynamicSharedMemorySize, CONV_SMEM);

    // weight prep (split + pack)
    prep_w_split<<<( 576*256 + 255)/256, 256>>>(off_w1, wTs + WS_C1,  1152, 256, 256);
    prep_w_split<<<(1152*128 + 255)/256, 256>>>(off_w2, wTs + WS_C2,  2304, 128, 128);
    prep_w_split<<<( 576*128 + 255)/256, 256>>>(off_w3, wTs + WS_C3,  1152, 128, 128);
    prep_w_split<<<(2304*256 + 255)/256, 256>>>(lat_w,  wTs + WS_LAT, 4608, 256, 256);
    prep_w_split<<<(1152*128 + 255)/256, 256>>>(pred_w, wTs + WS_PRED,2304,  73, 128);
    transpose_dcn_w<<<144, 256>>>(dcn_w, wtb);

    // input activation splits
    act_split<<<(4194304 + 255)/256, 256>>>(cur, curS, 4194304, 0);
    act_split<<<(4194304 + 255)/256, 256>>>(sup, supS, 4194304, 0);

    // conv1: concat(cur,sup) -> c1 fp32
    conv3x3_bf<1,128,256,256,1,128,128,false,false>
        <<<dim3(512, 2), 256, CONV_SMEM>>>(curS, supS, nullptr, wTs + WS_C1, nullptr, c1);
    act_split<<<(16777216 + 255)/256, 256>>>(c1, c1Sr, 16777216, 0);
    act_split<<<(16777216 + 255)/256, 256>>>(c1, c1Sa, 16777216, 1);

    // conv2: c1(raw split) -> c2 fp32, stride 2
    conv3x3_bf<0,256,128,128,2,64,64,false,false>
        <<<dim3(128, 1), 256, CONV_SMEM>>>(c1Sr, nullptr, nullptr, wTs + WS_C2, nullptr, c2);
    act_split<<<(2097152 + 255)/256, 256>>>(c2, c2Sr, 2097152, 0);
    act_split<<<(2097152 + 255)/256, 256>>>(c2, c2Sa, 2097152, 1);

    // conv3: c2(raw split) -> c3 fp32, stride 2
    conv3x3_bf<0,128,128,128,2,32,32,false,false>
        <<<dim3(32, 1), 256, CONV_SMEM>>>(c2Sr, nullptr, nullptr, wTs + WS_C3, nullptr, c3);
    act_split<<<(524288 + 255)/256, 256>>>(c3, c3Sa, 524288, 1);

    // lat: relu-concat(c1, up2(c2), up4(c3)) -> relu(conv+bias), fp32
    conv3x3_bf<2,512,256,256,1,128,128,true,true>
        <<<dim3(512, 2), 256, CONV_SMEM>>>(c1Sa, c2Sa, c3Sa, wTs + WS_LAT, lat_b, lat);
    act_split<<<(16777216 + 255)/256, 256>>>(lat, latS, 16777216, 0);

    // pred: lat(split) -> ow fp32
    conv3x3_bf<0,256,73,128,1,128,128,true,false>
        <<<dim3(512, 1), 256, CONV_SMEM>>>(latS, nullptr, nullptr, wTs + WS_PRED, pred_b, owb);

    deform_kernel<<<2048, 128>>>(sup, owb, wtb, out);
    weight_relu_kernel<<<256, 256>>>(owb, out + 4 * 64 * 128 * 128);
}

// round 12
// speedup vs baseline: 1.0423x; 1.0423x over previous
#include <cuda_runtime.h>
#include <math.h>
#include <stdint.h>

// R11: 3xTF32 split MMA + per-tile drain (proven in R9 for bf16x6).
//  - half the issued tensor FLOPs of bf16x6 (3x k8 vs 6x k16)
//  - tf32 2-way split residual ~2^-24 => fp32-class products
//  - drain confines TC accumulate to 3 adds; long-K in fp32-RN FADD
//  - act_split machinery reverted (R10 proved scalar-pipe cost is hidden)
//  - prep merged so ncu -s 5 captures the LAT conv

// ---------------- scratch (device globals: allowed; no allocs) ----------------
__device__ float g_c1 [4*256*128*128]; // conv1 out (raw)             64 MB
__device__ float g_c2 [4*128* 64* 64]; // conv2 out (raw)              8 MB
__device__ float g_c3 [4*128* 32* 32]; // conv3 out (raw)              2 MB
__device__ float g_lat[4*256*128*128]; // lat out (relu'd)            64 MB
__device__ float g_ow [4* 73*128*128]; // pred out (raw)              19 MB
__device__ float g_wt [4*144*64];      // dcn_w transposed [g][c*9+k][o]
__device__ float g_wT [2211840];       // conv weights: [k][m] padded fp32

// wT offsets (floats)
#define WT_C1   0          // 1152*256
#define WT_C2   294912     // 2304*128
#define WT_C3   589824     // 1152*128
#define WT_LAT  737280     // 4608*256
#define WT_PRED 1916928    // 2304*128

__device__ __forceinline__ unsigned to_tf32_bits(float x) {
    unsigned y;
    asm("cvt.rna.tf32.f32 %0, %1;" : "=r"(y) : "f"(x));
    return y;
}
// split v = hi + lo (both tf32); residual ~2^-24*|v|
__device__ __forceinline__ void tf32_split(float v, unsigned& hi, unsigned& lo) {
    hi = to_tf32_bits(v);
    lo = to_tf32_bits(v - __uint_as_float(hi));
}

__device__ __forceinline__ void mma_tf32(float (&d)[4], const unsigned (&a)[4],
                                         const unsigned (&b)[2]) {
    asm volatile(
        "mma.sync.aligned.m16n8k8.row.col.f32.tf32.tf32.f32 "
        "{%0,%1,%2,%3},{%4,%5,%6,%7},{%8,%9},{%0,%1,%2,%3};"
        : "+f"(d[0]), "+f"(d[1]), "+f"(d[2]), "+f"(d[3])
        : "r"(a[0]), "r"(a[1]), "r"(a[2]), "r"(a[3]), "r"(b[0]), "r"(b[1]));
}

// ------- merged weight prep: all 5 convs, [COUT][K] -> [K][MP] fp32 -------
__global__ void prep_w_all(const float* __restrict__ w1, const float* __restrict__ w2,
                           const float* __restrict__ w3, const float* __restrict__ wl,
                           const float* __restrict__ wp, float* __restrict__ wT)
{
    int idx = blockIdx.x * 256 + threadIdx.x;
    if (idx >= 2211840) return;
    const float* w; int K, COUT, MP, base;
    if      (idx < 294912)  { w = w1; K = 1152; COUT = 256; MP = 256; base = WT_C1; }
    else if (idx < 589824)  { w = w2; K = 2304; COUT = 128; MP = 128; base = WT_C2; }
    else if (idx < 737280)  { w = w3; K = 1152; COUT = 128; MP = 128; base = WT_C3; }
    else if (idx < 1916928) { w = wl; K = 4608; COUT = 256; MP = 256; base = WT_LAT; }
    else                    { w = wp; K = 2304; COUT =  73; MP = 128; base = WT_PRED; }
    int loc = idx - base;
    int m = loc % MP;
    int k = loc / MP;
    wT[idx] = (m < COUT) ? w[(size_t)m * K + k] : 0.f;
}

// ---------------- 3xTF32 tensor-core implicit-GEMM 3x3 conv ----------------
// M = COUT (padded to MP), N = B*OH*OW, K = CIN*9.  128x128 tile, BK=16.
// 8 warps: warp tile 64x32 = 4x4 m16n8k8, 3 MMAs each into zeroed tmp,
// drained to fp32 regs. Double-buffered fp32 smem, SA=136.
// MODE 0: plain p0; MODE 1: concat(cur,sup); MODE 2: relu-concat(c1,up2(c2),up4(c3)).
template<int MODE, int CIN, int COUT, int MP, int STRIDE, int OH, int OW, bool RELU, bool HASBIAS>
__global__ __launch_bounds__(256, 2)
void conv3x3_tc(const float* __restrict__ p0, const float* __restrict__ p1,
                const float* __restrict__ p2, const float* __restrict__ wT,
                const float* __restrict__ bias, float* __restrict__ out)
{
    constexpr int K   = CIN * 9;
    constexpr int KT  = K / 16;
    constexpr int IH  = OH * STRIDE;
    constexpr int IW  = OW * STRIDE;
    constexpr int OHW = OH * OW;
    constexpr int SA  = 136;

    __shared__ float As[2][16 * SA];
    __shared__ float Bs[2][16 * SA];

    const int tid  = threadIdx.x;
    const int lane = tid & 31;
    const int wid  = tid >> 5;
    const int l4   = lane & 3;
    const int l8   = lane >> 2;
    const int m0   = blockIdx.y * 128;
    const int n0   = blockIdx.x * 128;
    const int warp_m = (wid >> 2) * 64;
    const int warp_n = (wid & 3) * 32;

    const int nn  = tid & 127;
    const int kk  = tid >> 7;
    const int n   = n0 + nn;
    const int b   = n / OHW;
    const int rem = n - b * OHW;
    const int oy  = rem / OW;
    const int ox  = rem - oy * OW;
    const int iy0 = oy * STRIDE - 1;
    const int ix0 = ox * STRIDE - 1;
    int ci0 = (kk * 8) / 9;
    int rr0 = kk * 8 - ci0 * 9;

    float4 areg0, areg1;
    float  breg[8];

    float acc[4][4][4];
    #pragma unroll
    for (int i = 0; i < 4; i++)
        #pragma unroll
        for (int j = 0; j < 4; j++)
            #pragma unroll
            for (int r = 0; r < 4; r++) acc[i][j][r] = 0.f;

    auto gatherA = [&](int kt) {
        const float* p = wT + (size_t)(kt * 16 + wid) * MP + m0 + (lane << 2);
        areg0 = *(const float4*)p;
        areg1 = *(const float4*)(p + 8 * MP);
    };

    auto gatherB = [&]() {
        #pragma unroll
        for (int h = 0; h < 8; h++) {
            int rr = rr0 + h, ci = ci0;
            if (rr >= 9) { rr -= 9; ci += 1; }
            int ky = (rr * 11) >> 5;
            int kx = rr - ky * 3;
            int iy = iy0 + ky;
            int ix = ix0 + kx;
            bool ok = ((unsigned)iy < (unsigned)IH) && ((unsigned)ix < (unsigned)IW);
            float v = 0.f;
            if (ok) {
                if (MODE == 0) {
                    v = p0[(((size_t)b * CIN + ci) * IH + iy) * IW + ix];
                } else if (MODE == 1) {
                    const float* p = (ci < 64) ? p0 : p1;
                    v = p[(((size_t)b * 64 + (ci & 63)) * 128 + iy) * 128 + ix];
                } else {
                    float t;
                    if (ci < 256)
                        t = p0[(((size_t)b * 256 + ci) * 128 + iy) * 128 + ix];
                    else if (ci < 384)
                        t = p1[(((size_t)b * 128 + (ci - 256)) * 64 + (iy >> 1)) * 64 + (ix >> 1)];
                    else
                        t = p2[(((size_t)b * 128 + (ci - 384)) * 32 + (iy >> 2)) * 32 + (ix >> 2)];
                    v = fmaxf(t, 0.f);
                }
            }
            breg[h] = v;
        }
        ci0 += 1; rr0 += 7;
        if (rr0 >= 9) { rr0 -= 9; ci0 += 1; }
    };

    auto storeA = [&](int buf) {
        float* a = &As[buf][wid * SA + (lane << 2)];
        *(float4*)a            = areg0;
        *(float4*)(a + 8 * SA) = areg1;
    };
    auto storeB = [&](int buf) {
        #pragma unroll
        for (int h = 0; h < 8; h++)
            Bs[buf][(kk * 8 + h) * SA + nn] = breg[h];
    };

    auto compute = [&](int buf) {
        #pragma unroll
        for (int kq = 0; kq < 2; kq++) {
            const float* as = &As[buf][(kq * 8 + l4) * SA];
            const float* bs = &Bs[buf][(kq * 8 + l4) * SA];
            unsigned bhi[4][2], blo[4][2];
            #pragma unroll
            for (int j = 0; j < 4; j++) {
                int nj = warp_n + 8 * j + l8;
                tf32_split(bs[nj],          bhi[j][0], blo[j][0]);
                tf32_split(bs[4 * SA + nj], bhi[j][1], blo[j][1]);
            }
            #pragma unroll
            for (int i = 0; i < 4; i++) {
                int mi = warp_m + 16 * i + l8;
                unsigned ahi[4], alo[4];
                tf32_split(as[mi],              ahi[0], alo[0]);
                tf32_split(as[mi + 8],          ahi[1], alo[1]);
                tf32_split(as[4 * SA + mi],     ahi[2], alo[2]);
                tf32_split(as[4 * SA + mi + 8], ahi[3], alo[3]);
                #pragma unroll
                for (int j = 0; j < 4; j++) {
                    // per-tile temp: TC rounding confined to 3 adds,
                    // long-K accumulation in fp32-RN below.
                    float tmp[4] = {0.f, 0.f, 0.f, 0.f};
                    mma_tf32(tmp, alo, bhi[j]);
                    mma_tf32(tmp, ahi, blo[j]);
                    mma_tf32(tmp, ahi, bhi[j]);
                    #pragma unroll
                    for (int r = 0; r < 4; r++)
                        acc[i][j][r] += tmp[r];
                }
            }
        }
    };

    gatherA(0); gatherB();
    storeA(0);  storeB(0);
    __syncthreads();
    #pragma unroll 1
    for (int kt = 0; kt < KT; kt++) {
        const int cur = kt & 1;
        if (kt + 1 < KT) { gatherA(kt + 1); gatherB(); }
        compute(cur);
        if (kt + 1 < KT) { storeA(cur ^ 1); storeB(cur ^ 1); }
        __syncthreads();
    }

    #pragma unroll
    for (int i = 0; i < 4; i++) {
        #pragma unroll
        for (int half = 0; half < 2; half++) {
            int m = m0 + warp_m + 16 * i + l8 + 8 * half;
            if (m >= COUT) continue;
            float bv = HASBIAS ? bias[m] : 0.f;
            #pragma unroll
            for (int j = 0; j < 4; j++) {
                int n2 = n0 + warp_n + 8 * j + 2 * l4;
                int b2 = n2 / OHW;
                int r2 = n2 - b2 * OHW;
                float v0 = acc[i][j][half * 2 + 0] + bv;
                float v1 = acc[i][j][half * 2 + 1] + bv;
                if (RELU) { v0 = fmaxf(v0, 0.f); v1 = fmaxf(v1, 0.f); }
                *(float2*)&out[((size_t)b2 * COUT + m) * OHW + r2] = make_float2(v0, v1);
            }
        }
    }
}

// ---------------- dcn weight transpose ----------------
__global__ void transpose_dcn_w(const float* __restrict__ dcn_w, float* __restrict__ wt)
{
    int e = blockIdx.x * 256 + threadIdx.x;
    if (e >= 4 * 144 * 64) return;
    int o   = e & 63;
    int gck = e >> 6;
    int g   = gck / 144;
    int ck  = gck - g * 144;
    int c   = ck / 9;
    int k   = ck - c * 9;
    wt[e] = dcn_w[((size_t)(o * 64 + g * 16 + c)) * 9 + k];
}

// ---------------- deformable conv (dg=4, Cg=16, K=3) ----------------
__global__ __launch_bounds__(128)
void deform_kernel(const float* __restrict__ sup,
                   const float* __restrict__ ow,
                   const float* __restrict__ wt,
                   float* __restrict__ out)
{
    __shared__ float s[144 * 32];
    const int t  = threadIdx.x;
    const int p0 = blockIdx.x * 32;
    const int og = t & 15;
    const int pg = t >> 4;

    float acc[4][4] = {};

    for (int g = 0; g < 4; g++) {
        if (g) __syncthreads();
        for (int tt = t; tt < 288; tt += 128) {
            int px = tt & 31;
            int k  = tt >> 5;
            int p  = p0 + px;
            int b  = p >> 14;
            int yx = p & 16383;
            int yy = yx >> 7;
            int xx = yx & 127;
            int ky = k / 3;
            int kx = k - ky * 3;
            int och = (g * 9 + k) * 2;
            const float* owb = ow + ((size_t)b * 73 + och) * 16384 + yx;
            float dy = owb[0];
            float dx = owb[16384];
            float py  = (float)(yy + ky - 1) + dy;
            float pxf = (float)(xx + kx - 1) + dx;
            float y0f = floorf(py), x0f = floorf(pxf);
            int   y0  = (int)y0f,  x0  = (int)x0f;
            float wy1 = py  - y0f, wx1 = pxf - x0f;
            float wy0 = 1.f - wy1, wx0 = 1.f - wx1;
            bool vy0 = (unsigned)y0       < 128u;
            bool vy1 = (unsigned)(y0 + 1) < 128u;
            bool vx0 = (unsigned)x0       < 128u;
            bool vx1 = (unsigned)(x0 + 1) < 128u;
            float w00 = (vy0 && vx0) ? wy0 * wx0 : 0.f;
            float w01 = (vy0 && vx1) ? wy0 * wx1 : 0.f;
            float w10 = (vy1 && vx0) ? wy1 * wx0 : 0.f;
            float w11 = (vy1 && vx1) ? wy1 * wx1 : 0.f;
            int yc0 = min(max(y0, 0), 127);
            int yc1 = min(max(y0 + 1, 0), 127);
            int xc0 = min(max(x0, 0), 127);
            int xc1 = min(max(x0 + 1, 0), 127);
            const float* fb = sup + ((size_t)b * 64 + g * 16) * 16384;
            int i00 = yc0 * 128 + xc0, i01 = yc0 * 128 + xc1;
            int i10 = yc1 * 128 + xc0, i11 = yc1 * 128 + xc1;
            #pragma unroll
            for (int c = 0; c < 16; c++) {
                const float* f = fb + c * 16384;
                float v = w00 * f[i00] + w01 * f[i01] + w10 * f[i10] + w11 * f[i11];
                s[(c * 9 + k) * 32 + px] = v;
            }
        }
        __syncthreads();
        const float* wg = wt + g * 144 * 64;
        #pragma unroll 4
        for (int ck = 0; ck < 144; ck++) {
            float4 v4 = *(const float4*)&s[ck * 32 + pg * 4];
            float4 w4 = __ldg((const float4*)(wg + ck * 64 + og * 4));
            float v[4]  = {v4.x, v4.y, v4.z, v4.w};
            float wv[4] = {w4.x, w4.y, w4.z, w4.w};
            #pragma unroll
            for (int i = 0; i < 4; i++)
                #pragma unroll
                for (int j = 0; j < 4; j++)
                    acc[i][j] = fmaf(v[i], wv[j], acc[i][j]);
        }
    }

    #pragma unroll
    for (int i = 0; i < 4; i++) {
        int p  = p0 + pg * 4 + i;
        int b  = p >> 14;
        int yx = p & 16383;
        #pragma unroll
        for (int j = 0; j < 4; j++) {
            int o = og * 4 + j;
            out[((size_t)b * 64 + o) * 16384 + yx] = acc[i][j];
        }
    }
}

// ---------------- weight channel: relu(ow[:,72]) ----------------
__global__ void weight_relu_kernel(const float* __restrict__ ow, float* __restrict__ out2)
{
    int i  = blockIdx.x * 256 + threadIdx.x;
    int b  = i >> 14;
    int yx = i & 16383;
    out2[i] = fmaxf(ow[((size_t)b * 73 + 72) * 16384 + yx], 0.f);
}

// ---------------- launch ----------------
extern "C" void kernel_launch(void* const* d_in, const int* in_sizes, int n_in,
                              void* d_out, int out_size)
{
    const float* cur    = (const float*)d_in[0];
    const float* sup    = (const float*)d_in[1];
    const float* off_w1 = (const float*)d_in[3];
    const float* off_w2 = (const float*)d_in[4];
    const float* off_w3 = (const float*)d_in[5];
    const float* lat_w  = (const float*)d_in[6];
    const float* lat_b  = (const float*)d_in[7];
    const float* pred_w = (const float*)d_in[8];
    const float* pred_b = (const float*)d_in[9];
    const float* dcn_w  = (const float*)d_in[10];
    float* out = (float*)d_out;

    float *c1, *c2, *c3, *lat, *owb, *wtb, *wT;
    cudaGetSymbolAddress((void**)&c1,  g_c1);
    cudaGetSymbolAddress((void**)&c2,  g_c2);
    cudaGetSymbolAddress((void**)&c3,  g_c3);
    cudaGetSymbolAddress((void**)&lat, g_lat);
    cudaGetSymbolAddress((void**)&owb, g_ow);
    cudaGetSymbolAddress((void**)&wtb, g_wt);
    cudaGetSymbolAddress((void**)&wT,  g_wT);

    // launch 0: merged weight prep; launch 1: dcn transpose
    prep_w_all<<<(2211840 + 255)/256, 256>>>(off_w1, off_w2, off_w3, lat_w, pred_w, wT);
    transpose_dcn_w<<<144, 256>>>(dcn_w, wtb);

    // launch 2: conv1: concat(cur,sup) -> c1 [4,256,128,128]
    conv3x3_tc<1,128,256,256,1,128,128,false,false>
        <<<dim3(512, 2), 256>>>(cur, sup, nullptr, wT + WT_C1, nullptr, c1);
    // launch 3: conv2: c1 -> c2 [4,128,64,64], stride 2
    conv3x3_tc<0,256,128,128,2,64,64,false,false>
        <<<dim3(128, 1), 256>>>(c1, nullptr, nullptr, wT + WT_C2, nullptr, c2);
    // launch 4: conv3: c2 -> c3 [4,128,32,32], stride 2
    conv3x3_tc<0,128,128,128,2,32,32,false,false>
        <<<dim3(32, 1), 256>>>(c2, nullptr, nullptr, wT + WT_C3, nullptr, c3);
    // launch 5 (ncu target): lat: relu-concat(c1, up2(c2), up4(c3)) -> relu(conv+bias)
    conv3x3_tc<2,512,256,256,1,128,128,true,true>
        <<<dim3(512, 2), 256>>>(c1, c2, c3, wT + WT_LAT, lat_b, lat);
    // launch 6: pred: lat -> ow [4,73,128,128]
    conv3x3_tc<0,256,73,128,1,128,128,false,true>
        <<<dim3(512, 1), 256>>>(lat, nullptr, nullptr, wT + WT_PRED, pred_b, owb);

    deform_kernel<<<2048, 128>>>(sup, owb, wtb, out);
    weight_relu_kernel<<<256, 256>>>(owb, out + 4 * 64 * 128 * 128);
}

// round 13
// speedup vs baseline: 1.2731x; 1.2215x over previous
#include <cuda_runtime.h>
#include <math.h>
#include <stdint.h>

// R13: issue-slot diet for the 3xTF32+drain conv engine.
//  - one 6-MMA tmp chain per (i,j) spanning both kq (R9-proven depth), single drain
//  - mma_init (D=A*B+0) removes zero-inits
//  - A pre-split (hi/lo) in prep; B split at compute (relu folded for MODE2)
//  - cp.async gathers with zfill predicates (2 syncs/tile, no reg pipeline)
//  - conv2 split-K=2 + deterministic reduce (grid 128->256)
// Launch order keeps lat conv at ncu index 5.

// ---------------- scratch (device globals: allowed; no allocs) ----------------
__device__ float g_c1  [4*256*128*128]; // conv1 out                  64 MB
__device__ float g_c2  [4*128* 64* 64]; // conv2 out (reduced)         8 MB
__device__ float g_c3  [4*128* 32* 32]; // conv3 out                   2 MB
__device__ float g_lat [4*256*128*128]; // lat out (relu'd)           64 MB
__device__ float g_ow  [4* 73*128*128]; // pred out                   19 MB
__device__ float g_wt  [4*144*64];      // dcn_w transposed
__device__ float g_wThi[2211840];       // conv weights hi plane [k][m]
__device__ float g_wTlo[2211840];       // conv weights lo plane [k][m]
__device__ float g_part[2*2097152];     // conv2 split-K partials     16 MB

// wT offsets (floats)
#define WT_C1   0
#define WT_C2   294912
#define WT_C3   589824
#define WT_LAT  737280
#define WT_PRED 1916928

__device__ __forceinline__ unsigned to_tf32_bits(float x) {
    unsigned y;
    asm("cvt.rna.tf32.f32 %0, %1;" : "=r"(y) : "f"(x));
    return y;
}
__device__ __forceinline__ void tf32_split(float v, unsigned& hi, unsigned& lo) {
    hi = to_tf32_bits(v);
    lo = to_tf32_bits(v - __uint_as_float(hi));
}

__device__ __forceinline__ void mma_tf32(float (&d)[4], const unsigned (&a)[4],
                                         const unsigned (&b)[2]) {
    asm volatile(
        "mma.sync.aligned.m16n8k8.row.col.f32.tf32.tf32.f32 "
        "{%0,%1,%2,%3},{%4,%5,%6,%7},{%8,%9},{%0,%1,%2,%3};"
        : "+f"(d[0]), "+f"(d[1]), "+f"(d[2]), "+f"(d[3])
        : "r"(a[0]), "r"(a[1]), "r"(a[2]), "r"(a[3]), "r"(b[0]), "r"(b[1]));
}
// D = A*B + 0 (initializes tmp without zero-MOVs)
__device__ __forceinline__ void mma_tf32_init(float (&d)[4], const unsigned (&a)[4],
                                              const unsigned (&b)[2]) {
    asm volatile(
        "mma.sync.aligned.m16n8k8.row.col.f32.tf32.tf32.f32 "
        "{%0,%1,%2,%3},{%4,%5,%6,%7},{%8,%9},{%10,%11,%12,%13};"
        : "=f"(d[0]), "=f"(d[1]), "=f"(d[2]), "=f"(d[3])
        : "r"(a[0]), "r"(a[1]), "r"(a[2]), "r"(a[3]), "r"(b[0]), "r"(b[1]),
          "f"(0.f), "f"(0.f), "f"(0.f), "f"(0.f));
}

// ---- cp.async helpers ----
__device__ __forceinline__ void cp4z(unsigned dst, const void* src, bool ok) {
    asm volatile("cp.async.ca.shared.global [%0], [%1], 4, %2;"
                 :: "r"(dst), "l"(src), "r"(ok ? 4 : 0));
}
__device__ __forceinline__ void cp16(unsigned dst, const void* src) {
    asm volatile("cp.async.cg.shared.global [%0], [%1], 16;" :: "r"(dst), "l"(src));
}
__device__ __forceinline__ void cp_commit() {
    asm volatile("cp.async.commit_group;");
}
template<int N> __device__ __forceinline__ void cp_wait() {
    asm volatile("cp.async.wait_group %0;" :: "n"(N));
}

// ------- merged weight prep: [COUT][K] -> hi/lo planes [K][MP] -------
__global__ void prep_w_all(const float* __restrict__ w1, const float* __restrict__ w2,
                           const float* __restrict__ w3, const float* __restrict__ wl,
                           const float* __restrict__ wp,
                           float* __restrict__ whi, float* __restrict__ wlo)
{
    int idx = blockIdx.x * 256 + threadIdx.x;
    if (idx >= 2211840) return;
    const float* w; int K, COUT, MP, base;
    if      (idx < 294912)  { w = w1; K = 1152; COUT = 256; MP = 256; base = WT_C1; }
    else if (idx < 589824)  { w = w2; K = 2304; COUT = 128; MP = 128; base = WT_C2; }
    else if (idx < 737280)  { w = w3; K = 1152; COUT = 128; MP = 128; base = WT_C3; }
    else if (idx < 1916928) { w = wl; K = 4608; COUT = 256; MP = 256; base = WT_LAT; }
    else                    { w = wp; K = 2304; COUT =  73; MP = 128; base = WT_PRED; }
    int loc = idx - base;
    int m = loc % MP;
    int k = loc / MP;
    float v = (m < COUT) ? w[(size_t)m * K + k] : 0.f;
    unsigned hi, lo;
    tf32_split(v, hi, lo);
    whi[idx] = __uint_as_float(hi);
    wlo[idx] = __uint_as_float(lo);
}

// ---------------- 3xTF32 split tensor-core implicit-GEMM 3x3 conv ----------------
// 128x128 tile, BK=16; 8 warps, warp tile 64x32 = 4x4 m16n8k8.
// A: pre-split hi/lo smem planes (cp.async 16B). B: raw fp32 smem (cp.async 4B zfill),
// split at compute (MODE2 also applies relu there).
// Per (i,j): 6-MMA tmp chain across both kq, then 4-FADD drain into fp32 acc.
template<int MODE, int CIN, int COUT, int MP, int STRIDE, int OH, int OW,
         bool RELU, bool HASBIAS, int KSPLIT>
__global__ __launch_bounds__(256, 2)
void conv3x3_tc(const float* __restrict__ p0, const float* __restrict__ p1,
                const float* __restrict__ p2,
                const float* __restrict__ whi, const float* __restrict__ wlo,
                const float* __restrict__ bias, float* __restrict__ out)
{
    constexpr int K    = CIN * 9;
    constexpr int KT   = K / 16;
    constexpr int KTP  = KT / KSPLIT;
    constexpr int IH   = OH * STRIDE;
    constexpr int IW   = OW * STRIDE;
    constexpr int OHW  = OH * OW;
    constexpr int SA   = 136;
    constexpr int TILE = 16 * SA;           // floats per (buf,plane)

    extern __shared__ float sm[];
    // layout: A hi/lo: [buf][plane][TILE] (4*TILE), then B: [buf][TILE] (2*TILE)
    float* Bsm = sm + 4 * TILE;

    const int tid  = threadIdx.x;
    const int lane = tid & 31;
    const int wid  = tid >> 5;
    const int l4   = lane & 3;
    const int l8   = lane >> 2;
    const int m0   = blockIdx.y * 128;
    const int n0   = blockIdx.x * 128;
    const int part = (KSPLIT > 1) ? blockIdx.z : 0;
    const int warp_m = (wid >> 2) * 64;
    const int warp_n = (wid & 3) * 32;

    unsigned smu  = (unsigned)__cvta_generic_to_shared(sm);
    unsigned smuB = (unsigned)__cvta_generic_to_shared(Bsm);

    // ---- B gather state ----
    const int nn  = tid & 127;
    const int kk  = tid >> 7;                 // 0/1
    const int n   = n0 + nn;
    const int b   = n / OHW;
    const int rem = n - b * OHW;
    const int oy  = rem / OW;
    const int ox  = rem - oy * OW;
    const int iy0 = oy * STRIDE - 1;
    const int ix0 = ox * STRIDE - 1;
    const int k0  = part * KTP * 16 + kk * 8;
    int ci0 = k0 / 9;
    int rr0 = k0 - ci0 * 9;

    float acc[4][4][4];
    #pragma unroll
    for (int i = 0; i < 4; i++)
        #pragma unroll
        for (int j = 0; j < 4; j++)
            #pragma unroll
            for (int r = 0; r < 4; r++) acc[i][j][r] = 0.f;

    // prefetch tile kt into buffer buf (cp.async only; advances B k-state)
    auto prefetch = [&](int kt, int buf) {
        // A: rows kt*16+wid and +8, both planes, 16B per lane
        {
            size_t rowoff = (size_t)(kt * 16 + wid) * MP + m0 + (lane << 2);
            unsigned d0 = smu + ((buf * 2 + 0) * TILE + wid * SA + (lane << 2)) * 4;
            unsigned d1 = smu + ((buf * 2 + 1) * TILE + wid * SA + (lane << 2)) * 4;
            cp16(d0,                whi + rowoff);
            cp16(d0 + 8 * SA * 4,   whi + rowoff + 8 * MP);
            cp16(d1,                wlo + rowoff);
            cp16(d1 + 8 * SA * 4,   wlo + rowoff + 8 * MP);
        }
        // B: 8 elements, 4B each with zfill predicate
        #pragma unroll
        for (int h = 0; h < 8; h++) {
            int rr = rr0 + h, ci = ci0;
            if (rr >= 9) { rr -= 9; ci += 1; }
            int ky = (rr * 11) >> 5;
            int kx = rr - ky * 3;
            int iy = iy0 + ky;
            int ix = ix0 + kx;
            bool ok = ((unsigned)iy < (unsigned)IH) && ((unsigned)ix < (unsigned)IW);
            const float* src;
            if (MODE == 0) {
                src = p0 + ((((size_t)b * CIN + ci) * IH + iy) * IW + ix);
            } else if (MODE == 1) {
                const float* p = (ci < 64) ? p0 : p1;
                src = p + ((((size_t)b * 64 + (ci & 63)) * 128 + iy) * 128 + ix);
            } else {
                if (ci < 256)
                    src = p0 + ((((size_t)b * 256 + ci) * 128 + iy) * 128 + ix);
                else if (ci < 384)
                    src = p1 + ((((size_t)b * 128 + (ci - 256)) * 64 + (iy >> 1)) * 64 + (ix >> 1));
                else
                    src = p2 + ((((size_t)b * 128 + (ci - 384)) * 32 + (iy >> 2)) * 32 + (ix >> 2));
            }
            unsigned d = smuB + (buf * TILE + (kk * 8 + h) * SA + nn) * 4;
            cp4z(d, src, ok);
        }
        ci0 += 1; rr0 += 7;
        if (rr0 >= 9) { rr0 -= 9; ci0 += 1; }
    };

    auto compute = [&](int buf) {
        const float* Ah = sm + (buf * 2 + 0) * TILE;
        const float* Al = sm + (buf * 2 + 1) * TILE;
        const float* Bv = Bsm + buf * TILE;

        // B fragments: both kq, split (MODE2: relu first)
        unsigned bhi[2][4][2], blo[2][4][2];
        #pragma unroll
        for (int kq = 0; kq < 2; kq++) {
            const float* bs = Bv + (kq * 8 + l4) * SA;
            #pragma unroll
            for (int j = 0; j < 4; j++) {
                int nj = warp_n + 8 * j + l8;
                float v0 = bs[nj];
                float v1 = bs[4 * SA + nj];
                if (MODE == 2) { v0 = fmaxf(v0, 0.f); v1 = fmaxf(v1, 0.f); }
                tf32_split(v0, bhi[kq][j][0], blo[kq][j][0]);
                tf32_split(v1, bhi[kq][j][1], blo[kq][j][1]);
            }
        }
        #pragma unroll
        for (int i = 0; i < 4; i++) {
            int mi = warp_m + 16 * i + l8;
            unsigned ah[2][4], al[2][4];
            #pragma unroll
            for (int kq = 0; kq < 2; kq++) {
                const float* ash = Ah + (kq * 8 + l4) * SA;
                const float* asl = Al + (kq * 8 + l4) * SA;
                ah[kq][0] = __float_as_uint(ash[mi]);
                ah[kq][1] = __float_as_uint(ash[mi + 8]);
                ah[kq][2] = __float_as_uint(ash[4 * SA + mi]);
                ah[kq][3] = __float_as_uint(ash[4 * SA + mi + 8]);
                al[kq][0] = __float_as_uint(asl[mi]);
                al[kq][1] = __float_as_uint(asl[mi + 8]);
                al[kq][2] = __float_as_uint(asl[4 * SA + mi]);
                al[kq][3] = __float_as_uint(asl[4 * SA + mi + 8]);
            }
            #pragma unroll
            for (int j = 0; j < 4; j++) {
                float tmp[4];
                mma_tf32_init(tmp, al[0], bhi[0][j]);   // cross terms first
                mma_tf32(tmp, ah[0], blo[0][j]);
                mma_tf32(tmp, al[1], bhi[1][j]);
                mma_tf32(tmp, ah[1], blo[1][j]);
                mma_tf32(tmp, ah[0], bhi[0][j]);        // mains last
                mma_tf32(tmp, ah[1], bhi[1][j]);
                #pragma unroll
                for (int r = 0; r < 4; r++)
                    acc[i][j][r] += tmp[r];             // fp32-RN long-K accum
            }
        }
    };

    // ---- cp.async double-buffered pipeline ----
    const int kt0 = part * KTP;
    const int kt1 = kt0 + KTP;
    int buf = 0;
    prefetch(kt0, 0);
    cp_commit();
    #pragma unroll 1
    for (int kt = kt0; kt < kt1; kt++) {
        if (kt + 1 < kt1) {
            prefetch(kt + 1, buf ^ 1);
            cp_commit();
            cp_wait<1>();
        } else {
            cp_wait<0>();
        }
        __syncthreads();
        compute(buf);
        __syncthreads();       // protect buf^1 before next prefetch overwrites
        buf ^= 1;
    }

    // ---- epilogue ----
    float* outp = out + (size_t)part * ((size_t)4 * COUT * OHW) * (KSPLIT > 1 ? 1 : 0);
    #pragma unroll
    for (int i = 0; i < 4; i++) {
        #pragma unroll
        for (int half = 0; half < 2; half++) {
            int m = m0 + warp_m + 16 * i + l8 + 8 * half;
            if (m >= COUT) continue;
            float bv = HASBIAS ? bias[m] : 0.f;
            #pragma unroll
            for (int j = 0; j < 4; j++) {
                int n2 = n0 + warp_n + 8 * j + 2 * l4;
                int b2 = n2 / OHW;
                int r2 = n2 - b2 * OHW;
                float v0 = acc[i][j][half * 2 + 0] + bv;
                float v1 = acc[i][j][half * 2 + 1] + bv;
                if (RELU) { v0 = fmaxf(v0, 0.f); v1 = fmaxf(v1, 0.f); }
                *(float2*)&outp[((size_t)b2 * COUT + m) * OHW + r2] = make_float2(v0, v1);
            }
        }
    }
}

#define CONV_SMEM ((4 * 16 * 136 + 2 * 16 * 136) * 4)   // 52224 B

// ---- split-K reduce: c2 = part0 + part1 (deterministic) ----
__global__ void reduce2_kernel(const float* __restrict__ p, float* __restrict__ o)
{
    int i = blockIdx.x * 256 + threadIdx.x;        // float4 index, n=2097152/4
    const float4* a = (const float4*)p;
    const float4* bq = (const float4*)(p + 2097152);
    float4 x = a[i], y = bq[i];
    ((float4*)o)[i] = make_float4(x.x + y.x, x.y + y.y, x.z + y.z, x.w + y.w);
}

// ---------------- dcn weight transpose ----------------
__global__ void transpose_dcn_w(const float* __restrict__ dcn_w, float* __restrict__ wt)
{
    int e = blockIdx.x * 256 + threadIdx.x;
    if (e >= 4 * 144 * 64) return;
    int o   = e & 63;
    int gck = e >> 6;
    int g   = gck / 144;
    int ck  = gck - g * 144;
    int c   = ck / 9;
    int k   = ck - c * 9;
    wt[e] = dcn_w[((size_t)(o * 64 + g * 16 + c)) * 9 + k];
}

// ---------------- deformable conv (dg=4, Cg=16, K=3) ----------------
__global__ __launch_bounds__(128)
void deform_kernel(const float* __restrict__ sup,
                   const float* __restrict__ ow,
                   const float* __restrict__ wt,
                   float* __restrict__ out)
{
    __shared__ float s[144 * 32];
    const int t  = threadIdx.x;
    const int p0 = blockIdx.x * 32;
    const int og = t & 15;
    const int pg = t >> 4;

    float acc[4][4] = {};

    for (int g = 0; g < 4; g++) {
        if (g) __syncthreads();
        for (int tt = t; tt < 288; tt += 128) {
            int px = tt & 31;
            int k  = tt >> 5;
            int p  = p0 + px;
            int b  = p >> 14;
            int yx = p & 16383;
            int yy = yx >> 7;
            int xx = yx & 127;
            int ky = k / 3;
            int kx = k - ky * 3;
            int och = (g * 9 + k) * 2;
            const float* owb = ow + ((size_t)b * 73 + och) * 16384 + yx;
            float dy = owb[0];
            float dx = owb[16384];
            float py  = (float)(yy + ky - 1) + dy;
            float pxf = (float)(xx + kx - 1) + dx;
            float y0f = floorf(py), x0f = floorf(pxf);
            int   y0  = (int)y0f,  x0  = (int)x0f;
            float wy1 = py  - y0f, wx1 = pxf - x0f;
            float wy0 = 1.f - wy1, wx0 = 1.f - wx1;
            bool vy0 = (unsigned)y0       < 128u;
            bool vy1 = (unsigned)(y0 + 1) < 128u;
            bool vx0 = (unsigned)x0       < 128u;
            bool vx1 = (unsigned)(x0 + 1) < 128u;
            float w00 = (vy0 && vx0) ? wy0 * wx0 : 0.f;
            float w01 = (vy0 && vx1) ? wy0 * wx1 : 0.f;
            float w10 = (vy1 && vx0) ? wy1 * wx0 : 0.f;
            float w11 = (vy1 && vx1) ? wy1 * wx1 : 0.f;
            int yc0 = min(max(y0, 0), 127);
            int yc1 = min(max(y0 + 1, 0), 127);
            int xc0 = min(max(x0, 0), 127);
            int xc1 = min(max(x0 + 1, 0), 127);
            const float* fb = sup + ((size_t)b * 64 + g * 16) * 16384;
            int i00 = yc0 * 128 + xc0, i01 = yc0 * 128 + xc1;
            int i10 = yc1 * 128 + xc0, i11 = yc1 * 128 + xc1;
            #pragma unroll
            for (int c = 0; c < 16; c++) {
                const float* f = fb + c * 16384;
                float v = w00 * f[i00] + w01 * f[i01] + w10 * f[i10] + w11 * f[i11];
                s[(c * 9 + k) * 32 + px] = v;
            }
        }
        __syncthreads();
        const float* wg = wt + g * 144 * 64;
        #pragma unroll 4
        for (int ck = 0; ck < 144; ck++) {
            float4 v4 = *(const float4*)&s[ck * 32 + pg * 4];
            float4 w4 = __ldg((const float4*)(wg + ck * 64 + og * 4));
            float v[4]  = {v4.x, v4.y, v4.z, v4.w};
            float wv[4] = {w4.x, w4.y, w4.z, w4.w};
            #pragma unroll
            for (int i = 0; i < 4; i++)
                #pragma unroll
                for (int j = 0; j < 4; j++)
                    acc[i][j] = fmaf(v[i], wv[j], acc[i][j]);
        }
    }

    #pragma unroll
    for (int i = 0; i < 4; i++) {
        int p  = p0 + pg * 4 + i;
        int b  = p >> 14;
        int yx = p & 16383;
        #pragma unroll
        for (int j = 0; j < 4; j++) {
            int o = og * 4 + j;
            out[((size_t)b * 64 + o) * 16384 + yx] = acc[i][j];
        }
    }
}

// ---------------- weight channel: relu(ow[:,72]) ----------------
__global__ void weight_relu_kernel(const float* __restrict__ ow, float* __restrict__ out2)
{
    int i  = blockIdx.x * 256 + threadIdx.x;
    int b  = i >> 14;
    int yx = i & 16383;
    out2[i] = fmaxf(ow[((size_t)b * 73 + 72) * 16384 + yx], 0.f);
}

// ---------------- launch ----------------
extern "C" void kernel_launch(void* const* d_in, const int* in_sizes, int n_in,
                              void* d_out, int out_size)
{
    const float* cur    = (const float*)d_in[0];
    const float* sup    = (const float*)d_in[1];
    const float* off_w1 = (const float*)d_in[3];
    const float* off_w2 = (const float*)d_in[4];
    const float* off_w3 = (const float*)d_in[5];
    const float* lat_w  = (const float*)d_in[6];
    const float* lat_b  = (const float*)d_in[7];
    const float* pred_w = (const float*)d_in[8];
    const float* pred_b = (const float*)d_in[9];
    const float* dcn_w  = (const float*)d_in[10];
    float* out = (float*)d_out;

    float *c1, *c2, *c3, *lat, *owb, *wtb, *whi, *wlo, *prt;
    cudaGetSymbolAddress((void**)&c1,  g_c1);
    cudaGetSymbolAddress((void**)&c2,  g_c2);
    cudaGetSymbolAddress((void**)&c3,  g_c3);
    cudaGetSymbolAddress((void**)&lat, g_lat);
    cudaGetSymbolAddress((void**)&owb, g_ow);
    cudaGetSymbolAddress((void**)&wtb, g_wt);
    cudaGetSymbolAddress((void**)&whi, g_wThi);
    cudaGetSymbolAddress((void**)&wlo, g_wTlo);
    cudaGetSymbolAddress((void**)&prt, g_part);

    cudaFuncSetAttribute(conv3x3_tc<1,128,256,256,1,128,128,false,false,1>,
                         cudaFuncAttributeMaxDynamicSharedMemorySize, CONV_SMEM);
    cudaFuncSetAttribute(conv3x3_tc<0,256,128,128,2,64,64,false,false,2>,
                         cudaFuncAttributeMaxDynamicSharedMemorySize, CONV_SMEM);
    cudaFuncSetAttribute(conv3x3_tc<0,128,128,128,2,32,32,false,false,1>,
                         cudaFuncAttributeMaxDynamicSharedMemorySize, CONV_SMEM);
    cudaFuncSetAttribute(conv3x3_tc<2,512,256,256,1,128,128,true,true,1>,
                         cudaFuncAttributeMaxDynamicSharedMemorySize, CONV_SMEM);
    cudaFuncSetAttribute(conv3x3_tc<0,256,73,128,1,128,128,false,true,1>,
                         cudaFuncAttributeMaxDynamicSharedMemorySize, CONV_SMEM);

    // launch 0: weight prep (transpose + tf32 hi/lo split)
    prep_w_all<<<(2211840 + 255)/256, 256>>>(off_w1, off_w2, off_w3, lat_w, pred_w,
                                             whi, wlo);
    // launch 1: conv1 concat(cur,sup) -> c1
    conv3x3_tc<1,128,256,256,1,128,128,false,false,1>
        <<<dim3(512, 2), 256, CONV_SMEM>>>(cur, sup, nullptr,
                                           whi + WT_C1, wlo + WT_C1, nullptr, c1);
    // launch 2: conv2 split-K=2 -> partials
    conv3x3_tc<0,256,128,128,2,64,64,false,false,2>
        <<<dim3(128, 1, 2), 256, CONV_SMEM>>>(c1, nullptr, nullptr,
                                              whi + WT_C2, wlo + WT_C2, nullptr, prt);
    // launch 3: reduce partials -> c2
    reduce2_kernel<<<2048, 256>>>(prt, c2);
    // launch 4: conv3 -> c3
    conv3x3_tc<0,128,128,128,2,32,32,false,false,1>
        <<<dim3(32, 1), 256, CONV_SMEM>>>(c2, nullptr, nullptr,
                                          whi + WT_C3, wlo + WT_C3, nullptr, c3);
    // launch 5 (ncu target): lat relu-concat(c1, up2(c2), up4(c3)) -> relu(conv+bias)
    conv3x3_tc<2,512,256,256,1,128,128,true,true,1>
        <<<dim3(512, 2), 256, CONV_SMEM>>>(c1, c2, c3,
                                           whi + WT_LAT, wlo + WT_LAT, lat_b, lat);
    // launch 6: pred -> ow
    conv3x3_tc<0,256,73,128,1,128,128,false,true,1>
        <<<dim3(512, 1), 256, CONV_SMEM>>>(lat, nullptr, nullptr,
                                           whi + WT_PRED, wlo + WT_PRED, pred_b, owb);

    transpose_dcn_w<<<144, 256>>>(dcn_w, wtb);
    deform_kernel<<<2048, 128>>>(sup, owb, wtb, out);
    weight_relu_kernel<<<256, 256>>>(owb, out + 4 * 64 * 128 * 128);
}

// round 17
// speedup vs baseline: 1.4620x; 1.1484x over previous
#include <cuda_runtime.h>
#include <cuda_fp16.h>
#include <math.h>
#include <stdint.h>

// R17: resubmit of R16 fp16x3 engine (broker died pre-compile twice; same
// signature as R2/R3 and R14/R15 which both resolved on resubmit — no kernel
// evidence exists). fp16 mantissa (11b) == tf32 mantissa, so a 2-way fp16
// split gives the same 2^-22 product precision as 3xTF32 — but on m16n8k16
// (4096 FLOP/instr): 3 MMA instructions per k16 slab instead of 6. Legacy
// tensor pipe is per-instruction rate-limited (rt~16) => ~2x conv speedup.
// Drain granularity identical to R13 (3-chain per k16, fp32-RN long-K accum).
// Harness targets plain sm_100 — no tcgen05 available (R15 evidence).

// ---------------- scratch ----------------
__device__ float g_c1  [4*256*128*128];
__device__ float g_c2  [4*128* 64* 64];
__device__ float g_c3  [4*128* 32* 32];
__device__ float g_lat [4*256*128*128];
__device__ float g_ow  [4* 73*128*128];
__device__ float g_wt  [4*144*64];
__device__ float g_part[2*2097152];         // conv2 split-K partials
__device__ unsigned g_wHi[1105920];         // packed fp16 hi plane [kpair][MP]
__device__ unsigned g_wLo[1105920];         // packed fp16 lo plane

// packed-plane offsets (u32 words)
#define WP_C1   0
#define WP_C2   147456
#define WP_C3   294912
#define WP_LAT  368640
#define WP_PRED 958464

// ---------------- helpers ----------------
__device__ __forceinline__ void splitH(float v, unsigned short& h, unsigned short& l)
{
    __half a = __float2half_rn(v);
    float r = v - __half2float(a);
    __half b = __float2half_rn(r);
    h = __half_as_ushort(a);
    l = __half_as_ushort(b);
}
__device__ __forceinline__ unsigned packu(unsigned short lo, unsigned short hi)
{
    return (unsigned)lo | ((unsigned)hi << 16);   // even k low, odd k high
}

__device__ __forceinline__ void mma_f16(float (&d)[4], const unsigned (&a)[4],
                                        const unsigned (&b)[2])
{
    asm volatile(
        "mma.sync.aligned.m16n8k16.row.col.f32.f16.f16.f32 "
        "{%0,%1,%2,%3},{%4,%5,%6,%7},{%8,%9},{%0,%1,%2,%3};"
        : "+f"(d[0]), "+f"(d[1]), "+f"(d[2]), "+f"(d[3])
        : "r"(a[0]), "r"(a[1]), "r"(a[2]), "r"(a[3]), "r"(b[0]), "r"(b[1]));
}
__device__ __forceinline__ void mma_f16_init(float (&d)[4], const unsigned (&a)[4],
                                             const unsigned (&b)[2])
{
    asm volatile(
        "mma.sync.aligned.m16n8k16.row.col.f32.f16.f16.f32 "
        "{%0,%1,%2,%3},{%4,%5,%6,%7},{%8,%9},{%10,%11,%12,%13};"
        : "=f"(d[0]), "=f"(d[1]), "=f"(d[2]), "=f"(d[3])
        : "r"(a[0]), "r"(a[1]), "r"(a[2]), "r"(a[3]), "r"(b[0]), "r"(b[1]),
          "f"(0.f), "f"(0.f), "f"(0.f), "f"(0.f));
}

__device__ __forceinline__ void cp16(unsigned dst, const void* src) {
    asm volatile("cp.async.cg.shared.global [%0], [%1], 16;" :: "r"(dst), "l"(src));
}
__device__ __forceinline__ void cp_commit() { asm volatile("cp.async.commit_group;"); }
__device__ __forceinline__ void cp_wait0()  { asm volatile("cp.async.wait_group 0;"); }

// ------- weight prep: [COUT][K] fp32 -> packed fp16 hi/lo planes [kpair][MP] -------
__global__ void prep_w_all(const float* __restrict__ w1, const float* __restrict__ w2,
                           const float* __restrict__ w3, const float* __restrict__ wl,
                           const float* __restrict__ wp,
                           unsigned* __restrict__ whi, unsigned* __restrict__ wlo)
{
    int idx = blockIdx.x * 256 + threadIdx.x;
    if (idx >= 1105920) return;
    const float* w; int K, COUT, MP, base;
    if      (idx < 147456) { w = w1; K = 1152; COUT = 256; MP = 256; base = WP_C1; }
    else if (idx < 294912) { w = w2; K = 2304; COUT = 128; MP = 128; base = WP_C2; }
    else if (idx < 368640) { w = w3; K = 1152; COUT = 128; MP = 128; base = WP_C3; }
    else if (idx < 958464) { w = wl; K = 4608; COUT = 256; MP = 256; base = WP_LAT; }
    else                   { w = wp; K = 2304; COUT =  73; MP = 128; base = WP_PRED; }
    int loc = idx - base;
    int m  = loc % MP;
    int kp = loc / MP;
    float v0 = 0.f, v1 = 0.f;
    if (m < COUT) {
        v0 = w[(size_t)m * K + 2 * kp];
        v1 = w[(size_t)m * K + 2 * kp + 1];
    }
    unsigned short h0, l0, h1, l1;
    splitH(v0, h0, l0);
    splitH(v1, h1, l1);
    whi[idx] = packu(h0, h1);
    wlo[idx] = packu(l0, l1);
}

// ---------------- fp16x3 split tensor-core implicit-GEMM 3x3 conv ----------------
// 128(m) x 128(n) CTA tile, BK=32 (2 k16 slabs per tile). 8 warps, warp 64x32.
// A: packed fp16 hi/lo planes via cp.async. B: fp32 gather -> reg -> split+pack
// -> STS after compute (buf^1 free). Per (i,j) per slab: 3-MMA tmp chain,
// fp32-RN drain (R13 granularity).
template<int MODE, int CIN, int COUT, int MP, int STRIDE, int OH, int OW,
         bool RELU, bool HASBIAS, int KSPLIT>
__global__ __launch_bounds__(256, 2)
void conv3x3_f16(const float* __restrict__ p0, const float* __restrict__ p1,
                 const float* __restrict__ p2,
                 const unsigned* __restrict__ whi, const unsigned* __restrict__ wlo,
                 const float* __restrict__ bias, float* __restrict__ out)
{
    constexpr int K    = CIN * 9;
    constexpr int KT   = K / 32;
    constexpr int KTP  = KT / KSPLIT;
    constexpr int IH   = OH * STRIDE;
    constexpr int IW   = OW * STRIDE;
    constexpr int OHW  = OH * OW;
    constexpr int PR   = 132;                 // padded row stride (u32 words)
    constexpr int TILE = 16 * PR;             // words per (buf,plane): 16 kpairs

    extern __shared__ unsigned sm[];
    // A: [buf][plane][TILE] (4*TILE), then B: [buf][plane][TILE] (4*TILE)
    unsigned* Bsm = sm + 4 * TILE;

    const int tid  = threadIdx.x;
    const int lane = tid & 31;
    const int wid  = tid >> 5;
    const int l4   = lane & 3;
    const int l8   = lane >> 2;
    const int m0   = blockIdx.y * 128;
    const int n0   = blockIdx.x * 128;
    const int part = (KSPLIT > 1) ? blockIdx.z : 0;
    const int warp_m = (wid >> 2) * 64;
    const int warp_n = (wid & 3) * 32;

    unsigned smu = (unsigned)__cvta_generic_to_shared(sm);

    // ---- B gather geometry: n fixed per thread, 16 k's per tile ----
    const int nn  = tid & 127;
    const int kg  = tid >> 7;                 // 0/1 -> k base 16*kg within BK=32
    const int n   = n0 + nn;
    const int b   = n / OHW;
    const int rem = n - b * OHW;
    const int oy  = rem / OW;
    const int ox  = rem - oy * OW;
    const int iy0 = oy * STRIDE - 1;
    const int ix0 = ox * STRIDE - 1;
    const int k00 = part * KTP * 32 + kg * 16;
    int ci0 = k00 / 9;
    int rr0 = k00 - ci0 * 9;

    float vreg[16];

    float acc[4][4][4];
    #pragma unroll
    for (int i = 0; i < 4; i++)
        #pragma unroll
        for (int j = 0; j < 4; j++)
            #pragma unroll
            for (int r = 0; r < 4; r++) acc[i][j][r] = 0.f;

    // ---- A prefetch: 2 planes x 16 kpairs x 128 m words = 4096 w / 4 per cp16 ----
    auto prefetchA = [&](int kt, int buf) {
        #pragma unroll
        for (int i = 0; i < 4; i++) {
            int g    = tid + 256 * i;
            int p    = g >> 9;                // plane 0/1
            int r9   = g & 511;
            int kp   = r9 >> 5;               // 0..15
            int mseg = (r9 & 31) * 4;
            const unsigned* src = (p ? wlo : whi)
                + (size_t)(kt * 16 + kp) * MP + m0 + mseg;
            unsigned dst = smu + ((buf * 2 + p) * TILE + kp * PR + mseg) * 4;
            cp16(dst, src);
        }
    };

    // ---- B gather: 16 fp32 into regs (advances k-state by 32) ----
    auto gatherB = [&]() {
        #pragma unroll
        for (int h = 0; h < 16; h++) {
            int rr = rr0 + h, ci = ci0;
            if (rr >= 9) { rr -= 9; ci += 1; }
            if (rr >= 9) { rr -= 9; ci += 1; }
            int ky = (rr * 11) >> 5;
            int kx = rr - ky * 3;
            int iy = iy0 + ky;
            int ix = ix0 + kx;
            bool ok = ((unsigned)iy < (unsigned)IH) && ((unsigned)ix < (unsigned)IW);
            float v = 0.f;
            if (ok) {
                if (MODE == 0) {
                    v = p0[(((size_t)b * CIN + ci) * IH + iy) * IW + ix];
                } else if (MODE == 1) {
                    const float* p = (ci < 64) ? p0 : p1;
                    v = p[(((size_t)b * 64 + (ci & 63)) * 128 + iy) * 128 + ix];
                } else {
                    float t;
                    if (ci < 256)
                        t = p0[(((size_t)b * 256 + ci) * 128 + iy) * 128 + ix];
                    else if (ci < 384)
                        t = p1[(((size_t)b * 128 + (ci - 256)) * 64 + (iy >> 1)) * 64 + (ix >> 1)];
                    else
                        t = p2[(((size_t)b * 128 + (ci - 384)) * 32 + (iy >> 2)) * 32 + (ix >> 2)];
                    v = fmaxf(t, 0.f);
                }
            }
            vreg[h] = v;
        }
        ci0 += 3; rr0 += 5;
        if (rr0 >= 9) { rr0 -= 9; ci0 += 1; }
    };

    // ---- B split+pack+store: 8 words per plane at [kg*8+t][nn] ----
    auto storeB = [&](int buf) {
        #pragma unroll
        for (int t = 0; t < 8; t++) {
            unsigned short h0, l0, h1, l1;
            splitH(vreg[2 * t],     h0, l0);
            splitH(vreg[2 * t + 1], h1, l1);
            unsigned idx = (kg * 8 + t) * PR + nn;
            Bsm[(buf * 2 + 0) * TILE + idx] = packu(h0, h1);
            Bsm[(buf * 2 + 1) * TILE + idx] = packu(l0, l1);
        }
    };

    auto compute = [&](int buf) {
        const unsigned* Ah = sm  + (buf * 2 + 0) * TILE;
        const unsigned* Al = sm  + (buf * 2 + 1) * TILE;
        const unsigned* Bh = Bsm + (buf * 2 + 0) * TILE;
        const unsigned* Bl = Bsm + (buf * 2 + 1) * TILE;
        #pragma unroll
        for (int s = 0; s < 2; s++) {            // two k16 slabs
            int kp0 = s * 8 + l4;
            unsigned bh[4][2], bl[4][2];
            #pragma unroll
            for (int j = 0; j < 4; j++) {
                int nj = warp_n + 8 * j + l8;
                bh[j][0] = Bh[kp0 * PR + nj];
                bh[j][1] = Bh[(kp0 + 4) * PR + nj];
                bl[j][0] = Bl[kp0 * PR + nj];
                bl[j][1] = Bl[(kp0 + 4) * PR + nj];
            }
            #pragma unroll
            for (int i = 0; i < 4; i++) {
                int mi = warp_m + 16 * i + l8;
                unsigned ah[4], al[4];
                ah[0] = Ah[kp0 * PR + mi];
                ah[1] = Ah[kp0 * PR + mi + 8];
                ah[2] = Ah[(kp0 + 4) * PR + mi];
                ah[3] = Ah[(kp0 + 4) * PR + mi + 8];
                al[0] = Al[kp0 * PR + mi];
                al[1] = Al[kp0 * PR + mi + 8];
                al[2] = Al[(kp0 + 4) * PR + mi];
                al[3] = Al[(kp0 + 4) * PR + mi + 8];
                #pragma unroll
                for (int j = 0; j < 4; j++) {
                    float tmp[4];
                    mma_f16_init(tmp, al, bh[j]);   // cross terms first
                    mma_f16(tmp, ah, bl[j]);
                    mma_f16(tmp, ah, bh[j]);        // main last
                    #pragma unroll
                    for (int r = 0; r < 4; r++)
                        acc[i][j][r] += tmp[r];     // fp32-RN long-K accum
                }
            }
        }
    };

    // ---- pipeline: one sync per tile ----
    const int kt0 = part * KTP;
    const int kt1 = kt0 + KTP;
    gatherB();
    prefetchA(kt0, 0); cp_commit();
    storeB(0);
    cp_wait0();
    __syncthreads();
    #pragma unroll 1
    for (int kt = kt0; kt < kt1; kt++) {
        int buf = (kt - kt0) & 1;
        if (kt + 1 < kt1) {
            gatherB();                        // LDGs overlap compute below
            prefetchA(kt + 1, buf ^ 1); cp_commit();
        }
        compute(buf);
        if (kt + 1 < kt1) storeB(buf ^ 1);    // buf^1 free since last sync
        cp_wait0();
        __syncthreads();
    }

    // ---- epilogue ----
    float* outp = out + (size_t)part * ((size_t)4 * COUT * OHW) * (KSPLIT > 1 ? 1 : 0);
    #pragma unroll
    for (int i = 0; i < 4; i++) {
        #pragma unroll
        for (int half = 0; half < 2; half++) {
            int m = m0 + warp_m + 16 * i + l8 + 8 * half;
            if (m >= COUT) continue;
            float bv = HASBIAS ? bias[m] : 0.f;
            #pragma unroll
            for (int j = 0; j < 4; j++) {
                int n2 = n0 + warp_n + 8 * j + 2 * l4;
                int b2 = n2 / OHW;
                int r2 = n2 - b2 * OHW;
                float v0 = acc[i][j][half * 2 + 0] + bv;
                float v1 = acc[i][j][half * 2 + 1] + bv;
                if (RELU) { v0 = fmaxf(v0, 0.f); v1 = fmaxf(v1, 0.f); }
                *(float2*)&outp[((size_t)b2 * COUT + m) * OHW + r2] = make_float2(v0, v1);
            }
        }
    }
}

#define CONV_SMEM (8 * 16 * 132 * 4)   // 67584 B

// ---- split-K reduce: c2 = part0 + part1 ----
__global__ void reduce2_kernel(const float* __restrict__ p, float* __restrict__ o)
{
    int i = blockIdx.x * 256 + threadIdx.x;
    const float4* a  = (const float4*)p;
    const float4* bq = (const float4*)(p + 2097152);
    float4 x = a[i], y = bq[i];
    ((float4*)o)[i] = make_float4(x.x + y.x, x.y + y.y, x.z + y.z, x.w + y.w);
}

// ---------------- dcn weight transpose ----------------
__global__ void transpose_dcn_w(const float* __restrict__ dcn_w, float* __restrict__ wt)
{
    int e = blockIdx.x * 256 + threadIdx.x;
    if (e >= 4 * 144 * 64) return;
    int o   = e & 63;
    int gck = e >> 6;
    int g   = gck / 144;
    int ck  = gck - g * 144;
    int c   = ck / 9;
    int k   = ck - c * 9;
    wt[e] = dcn_w[((size_t)(o * 64 + g * 16 + c)) * 9 + k];
}

// ---------------- deformable conv (dg=4, Cg=16, K=3) ----------------
__global__ __launch_bounds__(128)
void deform_kernel(const float* __restrict__ sup,
                   const float* __restrict__ ow,
                   const float* __restrict__ wt,
                   float* __restrict__ out)
{
    __shared__ float s[144 * 32];
    const int t  = threadIdx.x;
    const int p0 = blockIdx.x * 32;
    const int og = t & 15;
    const int pg = t >> 4;

    float acc[4][4] = {};

    for (int g = 0; g < 4; g++) {
        if (g) __syncthreads();
        for (int tt = t; tt < 288; tt += 128) {
            int px = tt & 31;
            int k  = tt >> 5;
            int p  = p0 + px;
            int b  = p >> 14;
            int yx = p & 16383;
            int yy = yx >> 7;
            int xx = yx & 127;
            int ky = k / 3;
            int kx = k - ky * 3;
            int och = (g * 9 + k) * 2;
            const float* owb = ow + ((size_t)b * 73 + och) * 16384 + yx;
            float dy = owb[0];
            float dx = owb[16384];
            float py  = (float)(yy + ky - 1) + dy;
            float pxf = (float)(xx + kx - 1) + dx;
            float y0f = floorf(py), x0f = floorf(pxf);
            int   y0  = (int)y0f,  x0  = (int)x0f;
            float wy1 = py  - y0f, wx1 = pxf - x0f;
            float wy0 = 1.f - wy1, wx0 = 1.f - wx1;
            bool vy0 = (unsigned)y0       < 128u;
            bool vy1 = (unsigned)(y0 + 1) < 128u;
            bool vx0 = (unsigned)x0       < 128u;
            bool vx1 = (unsigned)(x0 + 1) < 128u;
            float w00 = (vy0 && vx0) ? wy0 * wx0 : 0.f;
            float w01 = (vy0 && vx1) ? wy0 * wx1 : 0.f;
            float w10 = (vy1 && vx0) ? wy1 * wx0 : 0.f;
            float w11 = (vy1 && vx1) ? wy1 * wx1 : 0.f;
            int yc0 = min(max(y0, 0), 127);
            int yc1 = min(max(y0 + 1, 0), 127);
            int xc0 = min(max(x0, 0), 127);
            int xc1 = min(max(x0 + 1, 0), 127);
            const float* fb = sup + ((size_t)b * 64 + g * 16) * 16384;
            int i00 = yc0 * 128 + xc0, i01 = yc0 * 128 + xc1;
            int i10 = yc1 * 128 + xc0, i11 = yc1 * 128 + xc1;
            #pragma unroll
            for (int c = 0; c < 16; c++) {
                const float* f = fb + c * 16384;
                float v = w00 * f[i00] + w01 * f[i01] + w10 * f[i10] + w11 * f[i11];
                s[(c * 9 + k) * 32 + px] = v;
            }
        }
        __syncthreads();
        const float* wg = wt + g * 144 * 64;
        #pragma unroll 4
        for (int ck = 0; ck < 144; ck++) {
            float4 v4 = *(const float4*)&s[ck * 32 + pg * 4];
            float4 w4 = __ldg((const float4*)(wg + ck * 64 + og * 4));
            float v[4]  = {v4.x, v4.y, v4.z, v4.w};
            float wv[4] = {w4.x, w4.y, w4.z, w4.w};
            #pragma unroll
            for (int i = 0; i < 4; i++)
                #pragma unroll
                for (int j = 0; j < 4; j++)
                    acc[i][j] = fmaf(v[i], wv[j], acc[i][j]);
        }
    }

    #pragma unroll
    for (int i = 0; i < 4; i++) {
        int p  = p0 + pg * 4 + i;
        int b  = p >> 14;
        int yx = p & 16383;
        #pragma unroll
        for (int j = 0; j < 4; j++) {
            int o = og * 4 + j;
            out[((size_t)b * 64 + o) * 16384 + yx] = acc[i][j];
        }
    }
}

// ---------------- weight channel: relu(ow[:,72]) ----------------
__global__ void weight_relu_kernel(const float* __restrict__ ow, float* __restrict__ out2)
{
    int i  = blockIdx.x * 256 + threadIdx.x;
    int b  = i >> 14;
    int yx = i & 16383;
    out2[i] = fmaxf(ow[((size_t)b * 73 + 72) * 16384 + yx], 0.f);
}

// ---------------- launch ----------------
extern "C" void kernel_launch(void* const* d_in, const int* in_sizes, int n_in,
                              void* d_out, int out_size)
{
    const float* cur    = (const float*)d_in[0];
    const float* sup    = (const float*)d_in[1];
    const float* off_w1 = (const float*)d_in[3];
    const float* off_w2 = (const float*)d_in[4];
    const float* off_w3 = (const float*)d_in[5];
    const float* lat_w  = (const float*)d_in[6];
    const float* lat_b  = (const float*)d_in[7];
    const float* pred_w = (const float*)d_in[8];
    const float* pred_b = (const float*)d_in[9];
    const float* dcn_w  = (const float*)d_in[10];
    float* out = (float*)d_out;

    float *c1, *c2, *c3, *lat, *owb, *wtb, *prt;
    unsigned *whi, *wlo;
    cudaGetSymbolAddress((void**)&c1,  g_c1);
    cudaGetSymbolAddress((void**)&c2,  g_c2);
    cudaGetSymbolAddress((void**)&c3,  g_c3);
    cudaGetSymbolAddress((void**)&lat, g_lat);
    cudaGetSymbolAddress((void**)&owb, g_ow);
    cudaGetSymbolAddress((void**)&wtb, g_wt);
    cudaGetSymbolAddress((void**)&prt, g_part);
    cudaGetSymbolAddress((void**)&whi, g_wHi);
    cudaGetSymbolAddress((void**)&wlo, g_wLo);

    cudaFuncSetAttribute(conv3x3_f16<1,128,256,256,1,128,128,false,false,1>,
                         cudaFuncAttributeMaxDynamicSharedMemorySize, CONV_SMEM);
    cudaFuncSetAttribute(conv3x3_f16<0,256,128,128,2,64,64,false,false,2>,
                         cudaFuncAttributeMaxDynamicSharedMemorySize, CONV_SMEM);
    cudaFuncSetAttribute(conv3x3_f16<0,128,128,128,2,32,32,false,false,1>,
                         cudaFuncAttributeMaxDynamicSharedMemorySize, CONV_SMEM);
    cudaFuncSetAttribute(conv3x3_f16<2,512,256,256,1,128,128,true,true,1>,
                         cudaFuncAttributeMaxDynamicSharedMemorySize, CONV_SMEM);
    cudaFuncSetAttribute(conv3x3_f16<0,256,73,128,1,128,128,false,true,1>,
                         cudaFuncAttributeMaxDynamicSharedMemorySize, CONV_SMEM);

    // launch 0: weight prep (fp16 hi/lo split + transpose + pack)
    prep_w_all<<<(1105920 + 255)/256, 256>>>(off_w1, off_w2, off_w3, lat_w, pred_w,
                                             whi, wlo);
    // launch 1: conv1 concat(cur,sup) -> c1
    conv3x3_f16<1,128,256,256,1,128,128,false,false,1>
        <<<dim3(512, 2), 256, CONV_SMEM>>>(cur, sup, nullptr,
                                           whi + WP_C1, wlo + WP_C1, nullptr, c1);
    // launch 2: conv2 split-K=2 -> partials
    conv3x3_f16<0,256,128,128,2,64,64,false,false,2>
        <<<dim3(128, 1, 2), 256, CONV_SMEM>>>(c1, nullptr, nullptr,
                                              whi + WP_C2, wlo + WP_C2, nullptr, prt);
    // launch 3: reduce partials -> c2
    reduce2_kernel<<<2048, 256>>>(prt, c2);
    // launch 4: conv3 -> c3
    conv3x3_f16<0,128,128,128,2,32,32,false,false,1>
        <<<dim3(32, 1), 256, CONV_SMEM>>>(c2, nullptr, nullptr,
                                          whi + WP_C3, wlo + WP_C3, nullptr, c3);
    // launch 5 (ncu target): lat relu-concat(c1, up2(c2), up4(c3))
    conv3x3_f16<2,512,256,256,1,128,128,true,true,1>
        <<<dim3(512, 2), 256, CONV_SMEM>>>(c1, c2, c3,
                                           whi + WP_LAT, wlo + WP_LAT, lat_b, lat);
    // launch 6: pred -> ow
    conv3x3_f16<0,256,73,128,1,128,128,false,true,1>
        <<<dim3(512, 1), 256, CONV_SMEM>>>(lat, nullptr, nullptr,
                                           whi + WP_PRED, wlo + WP_PRED, pred_b, owb);

    transpose_dcn_w<<<144, 256>>>(dcn_w, wtb);
    deform_kernel<<<2048, 128>>>(sup, owb, wtb, out);
    weight_relu_kernel<<<256, 256>>>(owb, out + 4 * 64 * 128 * 128);
}